// round 2
// baseline (speedup 1.0000x reference)
#include <cuda_runtime.h>
#include <math.h>

#define Bb   8
#define Cc   32
#define Ll   90000
#define DOWNL 22500
#define FLATN 1440000

#define TILE_T 256
#define SH_STR 292     // 288 cols (256 + 32 halo) padded
#define SO_STR 68      // 64 cols + pad (per-ss sub-tile, double buffered)

typedef unsigned long long ull;

// ---- scratch (device globals; no allocation allowed) ----
__device__ float g_hA[Bb*Cc*Ll];     // 92 MB
__device__ float g_hB[Bb*Cc*Ll];     // 92 MB
__device__ float g_skip[Bb*Cc*Ll];   // 92 MB
__device__ float g_y[Bb*FLATN];      // 46 MB
__device__ float g_o[Bb*64];

__device__ __forceinline__ float fsig(float x)  { return 1.0f / (1.0f + __expf(-x)); }
__device__ __forceinline__ float ftanh(float x) { return 2.0f * fsig(2.0f * x) - 1.0f; }

__device__ __forceinline__ ull ffma2(ull a, ull b, ull c) {
    ull d; asm("fma.rn.f32x2 %0, %1, %2, %3;" : "=l"(d) : "l"(a), "l"(b), "l"(c)); return d;
}
__device__ __forceinline__ ull fadd2(ull a, ull b) {
    ull d; asm("add.rn.f32x2 %0, %1, %2;" : "=l"(d) : "l"(a), "l"(b)); return d;
}
__device__ __forceinline__ ull pack2(float lo, float hi) {
    ull d; asm("mov.b64 %0, {%1, %2};" : "=l"(d) : "f"(lo), "f"(hi)); return d;
}
__device__ __forceinline__ float2 unpack2(ull v) {
    float2 r; asm("mov.b64 {%0, %1}, %2;" : "=f"(r.x), "=f"(r.y) : "l"(v)); return r;
}

union F4U2 { float4 f; ulonglong2 u; };

// ---------------- conv0: x[B,1,L] -> h0[B,32,L] (K=3, causal) ----------------
__global__ void conv0_kernel(const float* __restrict__ x,
                             const float* __restrict__ w0,
                             const float* __restrict__ b0)
{
    int t  = blockIdx.x * blockDim.x + threadIdx.x;
    int bc = blockIdx.y;
    if (t >= Ll) return;
    int b = bc >> 5, c = bc & 31;
    const float* xb = x + b * Ll;
    float wk0 = w0[c*3+0], wk1 = w0[c*3+1], wk2 = w0[c*3+2];
    float v = wk2 * xb[t] + b0[c];
    if (t >= 1) v += wk1 * xb[t-1];
    if (t >= 2) v += wk0 * xb[t-2];
    g_hA[(b*Cc + c)*Ll + t] = v;
}

// ---------------- one WaveNet block (f32x2 packed) ----------------
// SMEM layout (floats):
//   sWfgd: 32c*32k*8  = 8192  (dup pairs: wf0,wf0,wf1,wf1,wg0,wg0,wg1,wg1)
//   sWsrd: 32c*32k*4  = 4096  (dup pairs: ws,ws,wr,wr)
//   sH:    32*SH_STR  = 9344
//   sO:    2*32*SO_STR= 4352  (double buffered per-ss sub-tile)
// total 25984 floats = 103936 B -> 2 CTAs/SM
template<int DIL, bool FIRST>
__global__ void __launch_bounds__(256, 2)
wavenet_block(int ping,
              const float* __restrict__ Wf, const float* __restrict__ bf,
              const float* __restrict__ Wg, const float* __restrict__ bg,
              const float* __restrict__ Ws, const float* __restrict__ bs,
              const float* __restrict__ Wr, const float* __restrict__ br)
{
    extern __shared__ float smem[];
    float* sWfgd = smem;                       // 8192
    float* sWsrd = smem + 8192;                // 4096
    float* sH    = smem + 12288;               // 9344
    float* sObuf = smem + 12288 + 32*SH_STR;   // 4352

    const float* h_in  = ping ? g_hB : g_hA;
    float*       h_out = ping ? g_hA : g_hB;

    const int tid   = threadIdx.x;
    const int b     = blockIdx.y;
    const int tile0 = blockIdx.x * TILE_T;

    // pack duplicated weights into shared
    for (int e = tid; e < 1024; e += 256) {
        int o = e >> 5, k = e & 31;
        float wf0 = Wf[o*64 + k*2 + 0], wf1 = Wf[o*64 + k*2 + 1];
        float wg0 = Wg[o*64 + k*2 + 0], wg1 = Wg[o*64 + k*2 + 1];
        float4* p = (float4*)(sWfgd + e*8);
        p[0] = make_float4(wf0, wf0, wf1, wf1);
        p[1] = make_float4(wg0, wg0, wg1, wg1);
        float ws = Ws[o*32 + k], wr = Wr[o*32 + k];
        ((float4*)sWsrd)[e] = make_float4(ws, ws, wr, wr);
    }
    // load h tile with left halo of 32
    const float* hb = h_in + (size_t)b * Cc * Ll;
    for (int e = tid; e < 32*288; e += 256) {
        int k = e / 288, j = e - k*288;
        int gt = tile0 - 32 + j;
        sH[k*SH_STR + j] = (gt >= 0 && gt < Ll) ? hb[k*Ll + gt] : 0.0f;
    }
    __syncthreads();

    const int cp = tid >> 4;          // 0..15
    const int c0 = cp, c1 = cp + 16;
    const int q  = tid & 15;          // 0..15
    const ull bf0p = pack2(bf[c0], bf[c0]), bf1p = pack2(bf[c1], bf[c1]);
    const ull bg0p = pack2(bg[c0], bg[c0]), bg1p = pack2(bg[c1], bg[c1]);
    const ull bs0p = pack2(bs[c0], bs[c0]), bs1p = pack2(bs[c1], bs[c1]);
    const ull br0p = pack2(br[c0], br[c0]), br1p = pack2(br[c1], br[c1]);

    const float* wp0 = sWfgd + c0*256;
    const float* wp1 = sWfgd + c1*256;
    const float* vp0 = sWsrd + c0*128;
    const float* vp1 = sWsrd + c1*128;

    for (int ss = 0; ss < 4; ++ss) {
        const int tl = ss*64 + q*4;   // 0..255 (mult of 4)
        const int bt = 32 + tl;
        float* sO = sObuf + (ss & 1) * (32*SO_STR);

        ull f0a=bf0p, f0b=bf0p, g0a=bg0p, g0b=bg0p;
        ull f1a=bf1p, f1b=bf1p, g1a=bg1p, g1b=bg1p;

        #pragma unroll 4
        for (int k = 0; k < 32; ++k) {
            ulonglong2 wA0 = *(const ulonglong2*)(wp0 + k*8);      // wf0d, wf1d (c0)
            ulonglong2 wA1 = *(const ulonglong2*)(wp0 + k*8 + 4);  // wg0d, wg1d (c0)
            ulonglong2 wB0 = *(const ulonglong2*)(wp1 + k*8);
            ulonglong2 wB1 = *(const ulonglong2*)(wp1 + k*8 + 4);
            const float* row = sH + k*SH_STR;
            F4U2 vt; vt.f = *(const float4*)(row + bt);
            ull vs01, vs23;
            if (DIL >= 4) {
                ulonglong2 vv = *(const ulonglong2*)(row + bt - DIL);
                vs01 = vv.x; vs23 = vv.y;
            } else if (DIL == 2) {
                ulonglong2 vv = *(const ulonglong2*)(row + bt - 4);
                vs01 = vv.y; vs23 = vt.u.x;
            } else {
                float vpw = row[bt - 1];
                vs01 = pack2(vpw, vt.f.x);
                vs23 = pack2(vt.f.y, vt.f.z);
            }
            f0a = ffma2(wA0.x, vs01, f0a);  f0b = ffma2(wA0.x, vs23, f0b);
            f0a = ffma2(wA0.y, vt.u.x, f0a); f0b = ffma2(wA0.y, vt.u.y, f0b);
            g0a = ffma2(wA1.x, vs01, g0a);  g0b = ffma2(wA1.x, vs23, g0b);
            g0a = ffma2(wA1.y, vt.u.x, g0a); g0b = ffma2(wA1.y, vt.u.y, g0b);
            f1a = ffma2(wB0.x, vs01, f1a);  f1b = ffma2(wB0.x, vs23, f1b);
            f1a = ffma2(wB0.y, vt.u.x, f1a); f1b = ffma2(wB0.y, vt.u.y, f1b);
            g1a = ffma2(wB1.x, vs01, g1a);  g1b = ffma2(wB1.x, vs23, g1b);
            g1a = ffma2(wB1.y, vt.u.x, g1a); g1b = ffma2(wB1.y, vt.u.y, g1b);
        }
        {
            float2 F0a = unpack2(f0a), F0b = unpack2(f0b);
            float2 G0a = unpack2(g0a), G0b = unpack2(g0b);
            float2 F1a = unpack2(f1a), F1b = unpack2(f1b);
            float2 G1a = unpack2(g1a), G1b = unpack2(g1b);
            *(float4*)(sO + c0*SO_STR + q*4) = make_float4(
                ftanh(F0a.x)*fsig(G0a.x), ftanh(F0a.y)*fsig(G0a.y),
                ftanh(F0b.x)*fsig(G0b.x), ftanh(F0b.y)*fsig(G0b.y));
            *(float4*)(sO + c1*SO_STR + q*4) = make_float4(
                ftanh(F1a.x)*fsig(G1a.x), ftanh(F1a.y)*fsig(G1a.y),
                ftanh(F1b.x)*fsig(G1b.x), ftanh(F1b.y)*fsig(G1b.y));
        }
        __syncthreads();

        ull s0a=bs0p, s0b=bs0p, r0a=br0p, r0b=br0p;
        ull s1a=bs1p, s1b=bs1p, r1a=br1p, r1b=br1p;

        #pragma unroll 4
        for (int k = 0; k < 32; ++k) {
            ulonglong2 w0 = *(const ulonglong2*)(vp0 + k*4);   // wsd, wrd (c0)
            ulonglong2 w1 = *(const ulonglong2*)(vp1 + k*4);
            F4U2 ov; ov.f = *(const float4*)(sO + k*SO_STR + q*4);
            s0a = ffma2(w0.x, ov.u.x, s0a); s0b = ffma2(w0.x, ov.u.y, s0b);
            r0a = ffma2(w0.y, ov.u.x, r0a); r0b = ffma2(w0.y, ov.u.y, r0b);
            s1a = ffma2(w1.x, ov.u.x, s1a); s1b = ffma2(w1.x, ov.u.y, s1b);
            r1a = ffma2(w1.y, ov.u.x, r1a); r1b = ffma2(w1.y, ov.u.y, r1b);
        }

        int t = tile0 + tl;
        if (t < Ll) {
            F4U2 hv0; hv0.f = *(const float4*)(sH + c0*SH_STR + bt);
            F4U2 hv1; hv1.f = *(const float4*)(sH + c1*SH_STR + bt);
            size_t i0 = (size_t)(b*Cc + c0)*Ll + t;
            size_t i1 = (size_t)(b*Cc + c1)*Ll + t;
            F4U2 ho0, ho1;
            ho0.u.x = fadd2(hv0.u.x, r0a); ho0.u.y = fadd2(hv0.u.y, r0b);
            ho1.u.x = fadd2(hv1.u.x, r1a); ho1.u.y = fadd2(hv1.u.y, r1b);
            *(float4*)(h_out + i0) = ho0.f;
            *(float4*)(h_out + i1) = ho1.f;
            F4U2 sv0, sv1;
            if (!FIRST) {
                F4U2 p0; p0.f = *(const float4*)(g_skip + i0);
                F4U2 p1; p1.f = *(const float4*)(g_skip + i1);
                sv0.u.x = fadd2(p0.u.x, s0a); sv0.u.y = fadd2(p0.u.y, s0b);
                sv1.u.x = fadd2(p1.u.x, s1a); sv1.u.y = fadd2(p1.u.y, s1b);
            } else {
                sv0.u.x = s0a; sv0.u.y = s0b;
                sv1.u.x = s1a; sv1.u.y = s1b;
            }
            *(float4*)(g_skip + i0) = sv0.f;
            *(float4*)(g_skip + i1) = sv1.f;
        }
        // next ss writes the OTHER sO buffer; barrier before its loop2 protects reuse
    }
}

// ---------------- downsample conv: skip[B,32,L] -> y[B,64,22500] (K=4, stride 4) ----
__global__ void __launch_bounds__(256, 2)
downsample_kernel(const float* __restrict__ wd, const float* __restrict__ bd)
{
    extern __shared__ float smem[];
    float4* sWd = (float4*)smem;          // [64o][32c] float4 over j  (32 KB)
    float*  sSk = smem + 8192;            // [32][256]                 (32 KB)

    int tid = threadIdx.x;
    int b   = blockIdx.y;
    int u0  = blockIdx.x * 64;
    int t0  = u0 * 4;

    const float4* wd4 = (const float4*)wd;
    for (int e = tid; e < 2048; e += 256) sWd[e] = wd4[e];

    const float* skb = g_skip + (size_t)b * Cc * Ll;
    for (int e = tid; e < 32*256; e += 256) {
        int c = e >> 8, j = e & 255;
        int gt = t0 + j;
        sSk[c*256 + j] = (gt < Ll) ? skb[c*Ll + gt] : 0.0f;
    }
    __syncthreads();

    int op = tid >> 3;            // 0..31
    int o0 = op, o1 = op + 32;
    int qq = tid & 7;
    // packed over j: acc pairs (j0,j1) and (j2,j3)
    ull a0p[8], a0q[8], a1p[8], a1q[8];
    #pragma unroll
    for (int i = 0; i < 8; ++i) { a0p[i]=0; a0q[i]=0; a1p[i]=0; a1q[i]=0; }

    #pragma unroll 4
    for (int c = 0; c < 32; ++c) {
        F4U2 w0v; w0v.f = sWd[o0*32 + c];
        F4U2 w1v; w1v.f = sWd[o1*32 + c];
        const float* sr = sSk + c*256;
        #pragma unroll
        for (int i = 0; i < 8; ++i) {
            F4U2 sv; sv.f = *(const float4*)(sr + (i*8 + qq)*4);
            a0p[i] = ffma2(w0v.u.x, sv.u.x, a0p[i]);
            a0q[i] = ffma2(w0v.u.y, sv.u.y, a0q[i]);
            a1p[i] = ffma2(w1v.u.x, sv.u.x, a1p[i]);
            a1q[i] = ffma2(w1v.u.y, sv.u.y, a1q[i]);
        }
    }
    float* yb = g_y + (size_t)b * FLATN;
    float bd0 = bd[o0], bd1 = bd[o1];
    #pragma unroll
    for (int i = 0; i < 8; ++i) {
        int u = u0 + i*8 + qq;
        if (u < DOWNL) {
            float2 p = unpack2(a0p[i]), qd = unpack2(a0q[i]);
            yb[o0*DOWNL + u] = bd0 + p.x + p.y + qd.x + qd.y;
            float2 p1 = unpack2(a1p[i]), q1 = unpack2(a1q[i]);
            yb[o1*DOWNL + u] = bd1 + p1.x + p1.y + q1.x + q1.y;
        }
    }
}

// ---------------- FC: o[b,m] = sum_f fcW[m,f] * y[b,f] ----------------
__global__ void zero_o_kernel() {
    int i = threadIdx.x;
    if (i < Bb*64) g_o[i] = 0.0f;
}

#define FC_CHUNK 2000
__global__ void __launch_bounds__(512, 2)
fc_kernel(const float* __restrict__ fcW)
{
    extern __shared__ float smem[];          // sy[8][FC_CHUNK]
    int tid = threadIdx.x;
    int f0  = blockIdx.x * FC_CHUNK;
    int mg  = blockIdx.y;

    for (int e = tid; e < 8*FC_CHUNK/4; e += 512) {
        int b = e / (FC_CHUNK/4), f4 = e - b*(FC_CHUNK/4);
        ((float4*)smem)[b*(FC_CHUNK/4) + f4] =
            *(const float4*)(g_y + (size_t)b*FLATN + f0 + f4*4);
    }
    __syncthreads();

    int w = tid >> 5, lane = tid & 31;
    int m0 = mg*32 + w;
    float acc0[8], acc1[8];
    #pragma unroll
    for (int b = 0; b < 8; ++b) { acc0[b]=0.f; acc1[b]=0.f; }

    const float4* W0 = (const float4*)(fcW + (size_t)m0      * FLATN + f0);
    const float4* W1 = (const float4*)(fcW + (size_t)(m0+16) * FLATN + f0);
    for (int i4 = lane; i4 < FC_CHUNK/4; i4 += 32) {
        float4 wv0 = __ldg(W0 + i4);
        float4 wv1 = __ldg(W1 + i4);
        #pragma unroll
        for (int b = 0; b < 8; ++b) {
            float4 yv = ((const float4*)smem)[b*(FC_CHUNK/4) + i4];
            acc0[b] += wv0.x*yv.x + wv0.y*yv.y + wv0.z*yv.z + wv0.w*yv.w;
            acc1[b] += wv1.x*yv.x + wv1.y*yv.y + wv1.z*yv.z + wv1.w*yv.w;
        }
    }
    #pragma unroll
    for (int off = 16; off; off >>= 1) {
        #pragma unroll
        for (int b = 0; b < 8; ++b) {
            acc0[b] += __shfl_xor_sync(0xFFFFFFFFu, acc0[b], off);
            acc1[b] += __shfl_xor_sync(0xFFFFFFFFu, acc1[b], off);
        }
    }
    if (lane == 0) {
        #pragma unroll
        for (int b = 0; b < 8; ++b) {
            atomicAdd(&g_o[b*64 + m0],      acc0[b]);
            atomicAdd(&g_o[b*64 + m0 + 16], acc1[b]);
        }
    }
}

// ---------------- final: mu/logvar/z ----------------
__global__ void final_kernel(const float* __restrict__ eps,
                             const float* __restrict__ fcb,
                             float* __restrict__ out)
{
    int i = threadIdx.x;               // 0..255
    int b = i >> 5, l = i & 31;
    float mu = g_o[b*64 + l]      + fcb[l];
    float lv = g_o[b*64 + 32 + l] + fcb[32 + l];
    float z  = mu + eps[b*32 + l] * expf(0.5f * lv);
    out[i]       = mu;
    out[256 + i] = lv;
    out[512 + i] = z;
}

// ---------------- launch ----------------
extern "C" void kernel_launch(void* const* d_in, const int* in_sizes, int n_in,
                              void* d_out, int out_size)
{
    (void)in_sizes; (void)n_in; (void)out_size;
    const float* x   = (const float*)d_in[0];
    const float* eps = (const float*)d_in[1];
    const float* w0  = (const float*)d_in[2];
    const float* b0  = (const float*)d_in[3];
    const float* Wf  = (const float*)d_in[4];
    const float* bf  = (const float*)d_in[5];
    const float* Wg  = (const float*)d_in[6];
    const float* bg  = (const float*)d_in[7];
    const float* Ws  = (const float*)d_in[8];
    const float* bs  = (const float*)d_in[9];
    const float* Wr  = (const float*)d_in[10];
    const float* br  = (const float*)d_in[11];
    const float* wd  = (const float*)d_in[12];
    const float* bd  = (const float*)d_in[13];
    const float* fcW = (const float*)d_in[14];
    const float* fcb = (const float*)d_in[15];
    float* out = (float*)d_out;

    const int blkSmem = (8192 + 4096 + 32*SH_STR + 2*32*SO_STR) * 4;   // 103936 B
    cudaFuncSetAttribute(wavenet_block<1,true>,   cudaFuncAttributeMaxDynamicSharedMemorySize, blkSmem);
    cudaFuncSetAttribute(wavenet_block<2,false>,  cudaFuncAttributeMaxDynamicSharedMemorySize, blkSmem);
    cudaFuncSetAttribute(wavenet_block<4,false>,  cudaFuncAttributeMaxDynamicSharedMemorySize, blkSmem);
    cudaFuncSetAttribute(wavenet_block<8,false>,  cudaFuncAttributeMaxDynamicSharedMemorySize, blkSmem);
    cudaFuncSetAttribute(wavenet_block<16,false>, cudaFuncAttributeMaxDynamicSharedMemorySize, blkSmem);
    cudaFuncSetAttribute(wavenet_block<32,false>, cudaFuncAttributeMaxDynamicSharedMemorySize, blkSmem);
    cudaFuncSetAttribute(downsample_kernel, cudaFuncAttributeMaxDynamicSharedMemorySize, 65536);
    cudaFuncSetAttribute(fc_kernel,         cudaFuncAttributeMaxDynamicSharedMemorySize, 8*FC_CHUNK*4);

    const int tiles = (Ll + TILE_T - 1) / TILE_T;   // 352
    conv0_kernel<<<dim3(tiles, Bb*Cc), 256>>>(x, w0, b0);

    dim3 bg2(tiles, Bb);
    wavenet_block<1,true  ><<<bg2, 256, blkSmem>>>(0, Wf+0*2048, bf+0*32, Wg+0*2048, bg+0*32, Ws+0*1024, bs+0*32, Wr+0*1024, br+0*32);
    wavenet_block<2,false ><<<bg2, 256, blkSmem>>>(1, Wf+1*2048, bf+1*32, Wg+1*2048, bg+1*32, Ws+1*1024, bs+1*32, Wr+1*1024, br+1*32);
    wavenet_block<4,false ><<<bg2, 256, blkSmem>>>(0, Wf+2*2048, bf+2*32, Wg+2*2048, bg+2*32, Ws+2*1024, bs+2*32, Wr+2*1024, br+2*32);
    wavenet_block<8,false ><<<bg2, 256, blkSmem>>>(1, Wf+3*2048, bf+3*32, Wg+3*2048, bg+3*32, Ws+3*1024, bs+3*32, Wr+3*1024, br+3*32);
    wavenet_block<16,false><<<bg2, 256, blkSmem>>>(0, Wf+4*2048, bf+4*32, Wg+4*2048, bg+4*32, Ws+4*1024, bs+4*32, Wr+4*1024, br+4*32);
    wavenet_block<32,false><<<bg2, 256, blkSmem>>>(1, Wf+5*2048, bf+5*32, Wg+5*2048, bg+5*32, Ws+5*1024, bs+5*32, Wr+5*1024, br+5*32);

    downsample_kernel<<<dim3((DOWNL + 63)/64, Bb), 256, 65536>>>(wd, bd);
    zero_o_kernel<<<1, 512>>>();
    fc_kernel<<<dim3(FLATN/FC_CHUNK, 2), 512, 8*FC_CHUNK*4>>>(fcW);
    final_kernel<<<1, 256>>>(eps, fcb, out);
}